// round 11
// baseline (speedup 1.0000x reference)
#include <cuda_runtime.h>
#include <math.h>

#define VSZ 30000
#define DM  640
#define NL  6
#define NH  8
#define DHD 80
#define FFH 2560
#define BB  4
#define SSQ 33
#define EOS_TOK 2
#define NTH 1024

struct Params {
    const float *emb,*Wq,*bq,*Wk,*bk,*Wv,*bv,*Wo,*bo;
    const float *ln1s,*ln1b,*W1,*b1,*W2,*b2,*ln2s,*ln2b,*lmW,*lmb;
    float* out;                       // __output__ is float32 (hypothesis from rel_err invariant)
};

// ------------------------- device state -------------------------
__device__ int g_stop;
__device__ int g_inp[BB*SSQ];
__device__ float g_h [36*DM];
__device__ float g_h2[36*DM];
__device__ float g_q [36*DM];
__device__ float g_ao[36*DM];
__device__ float g_r1[36*DM];
__device__ float g_f1[36*FFH];
__device__ float g_r2[36*DM];
__device__ float g_kc[NL*BB*SSQ*DM];
__device__ float g_vc[NL*BB*SSQ*DM];

// ------------------------- init: prompt -> g_inp AND d_out (as float) -------------------------
__global__ void k_init(const int* words, float* out) {
    int t = threadIdx.x;
    if (t < BB*SSQ) g_inp[t] = 0;
    if (t < BB*32)  out[t] = 0.f;
    __syncthreads();
    if (t == 0) g_stop = 0;
    if (t < BB) g_inp[t*SSQ] = 1;                    // BOS
    if (t < 32) {
        int tok = words[t];
        g_inp[(t >> 3)*SSQ + 1 + (t & 7)] = tok;     // prompt into sequence
        out[(t >> 3)*32 + (t & 7)] = (float)tok;     // prompt into output cols 0..7
    }
}

// ------------------------- warp LayerNorm of one row (DM=640=32*20) ----------
__device__ __forceinline__ void ln_row_warp(const float* a, const float* r,
                                            const float* sc, const float* bi,
                                            float* dst) {
    int lane = threadIdx.x & 31;
    float v[20];
    float sum = 0.f;
#pragma unroll
    for (int i = 0; i < 20; i++) {
        float x = a[lane + 32*i] + r[lane + 32*i];
        v[i] = x; sum += x;
    }
#pragma unroll
    for (int o = 16; o > 0; o >>= 1) sum += __shfl_xor_sync(0xffffffffu, sum, o);
    float mean = sum / DM;
    float vs = 0.f;
#pragma unroll
    for (int i = 0; i < 20; i++) { float d = v[i] - mean; vs += d*d; }
#pragma unroll
    for (int o = 16; o > 0; o >>= 1) vs += __shfl_xor_sync(0xffffffffu, vs, o);
    float dn = sqrtf(vs / DM + 1e-6f);
#pragma unroll
    for (int i = 0; i < 20; i++)
        dst[lane + 32*i] = (v[i] - mean) / dn * sc[lane + 32*i] + bi[lane + 32*i];
}

// ------------------------- ONE generation step, ONE block -------------------------
template<int NC>
__global__ __launch_bounds__(NTH, 1)
void step_one(Params P, int p0, int cl) {
    if (g_stop) return;
    constexpr int M = 4*NC;
    const int t = threadIdx.x;
    const int warp = t >> 5, lane = t & 31;
    __shared__ int toks[M];
    __shared__ unsigned long long wbest[32][4];

    if (t < M) {
        int b = t / NC, j = t - b*NC;
        int tok = g_inp[b*SSQ + p0 + j];
        if (tok < 0 || tok >= VSZ) tok = 0;
        toks[t] = tok;
    }
    __syncthreads();

    // ---- embedding -> g_h ----
    for (int i = t; i < M*DM; i += NTH) {
        int r = i / DM, d = i - r*DM;
        g_h[i] = P.emb[(long long)toks[r]*DM + d];
    }
    __syncthreads();

    for (int l = 0; l < NL; l++) {
        const float* Wq = P.Wq + (long long)l*DM*DM;
        const float* Wk = P.Wk + (long long)l*DM*DM;
        const float* Wv = P.Wv + (long long)l*DM*DM;
        const float* Wo = P.Wo + (long long)l*DM*DM;
        const float* W1 = P.W1 + (long long)l*DM*FFH;
        const float* W2 = P.W2 + (long long)l*FFH*DM;

        // ---- QKV ----
        for (int i = t; i < 3*M*DM; i += NTH) {
            int sel = i / (M*DM), rem = i - sel*(M*DM);
            int m = rem / DM, n = rem - m*DM;
            const float* W    = (sel == 0) ? Wq : (sel == 1) ? Wk : Wv;
            const float* bias = ((sel == 0) ? P.bq : (sel == 1) ? P.bk : P.bv) + l*DM;
            const float* hp = g_h + m*DM;
            float acc = 0.f;
#pragma unroll 4
            for (int k = 0; k < DM; k++)
                acc = fmaf(hp[k], W[(long long)k*DM + n], acc);
            acc += bias[n];
            int b = m / NC, j = m - b*NC, p = p0 + j;
            if (sel == 0)      g_q[m*DM + n] = acc;
            else if (sel == 1) g_kc[((l*BB + b)*SSQ + p)*DM + n] = acc;
            else               g_vc[((l*BB + b)*SSQ + p)*DM + n] = acc;
        }
        __syncthreads();

        // ---- attention: one warp per (b,h,j) ----
        for (int tup = warp; tup < BB*NH*NC; tup += 32) {
            int b = tup / (NH*NC);
            int rem = tup - b*NH*NC;
            int h = rem / NC, j = rem - h*NC;
            int p = p0 + j, nk = p + 1;
            int r = b*NC + j;
            const float* qp = g_q + r*DM + h*DHD;
            float sc = -1e30f;
            if (lane < nk) {
                const float* kp = g_kc + ((l*BB + b)*SSQ + lane)*DM + h*DHD;
                float sv = 0.f;
#pragma unroll
                for (int d = 0; d < DHD; d++) sv = fmaf(qp[d], kp[d], sv);
                sc = sv / sqrtf((float)DHD);
            }
            float mx = sc;
            for (int o = 16; o > 0; o >>= 1)
                mx = fmaxf(mx, __shfl_xor_sync(0xffffffffu, mx, o));
            float e = (lane < nk) ? expf(sc - mx) : 0.f;
            float sum = e;
            for (int o = 16; o > 0; o >>= 1) sum += __shfl_xor_sync(0xffffffffu, sum, o);
            float o0 = 0.f, o1 = 0.f, o2 = 0.f;
            const float* vb = g_vc + ((l*BB + b)*SSQ)*DM + h*DHD;
            for (int jk = 0; jk < nk; jk++) {
                float pj = __shfl_sync(0xffffffffu, e, jk) / sum;
                const float* vp = vb + jk*DM;
                o0 = fmaf(pj, vp[lane],      o0);
                o1 = fmaf(pj, vp[lane + 32], o1);
                if (lane < 16) o2 = fmaf(pj, vp[lane + 64], o2);
            }
            float* ao = g_ao + r*DM + h*DHD;
            ao[lane] = o0; ao[lane + 32] = o1;
            if (lane < 16) ao[lane + 64] = o2;
        }
        __syncthreads();

        // ---- O-projection -> g_r1 ----
        for (int i = t; i < M*DM; i += NTH) {
            int m = i / DM, n = i - m*DM;
            const float* ap = g_ao + m*DM;
            float acc = 0.f;
#pragma unroll 4
            for (int k = 0; k < DM; k++)
                acc = fmaf(ap[k], Wo[(long long)k*DM + n], acc);
            g_r1[i] = acc + P.bo[l*DM + n];
        }
        __syncthreads();

        // ---- LN1: g_h2 = LN(g_h + g_r1) ----
        for (int r = warp; r < M; r += 32)
            ln_row_warp(g_h + r*DM, g_r1 + r*DM,
                        P.ln1s + l*DM, P.ln1b + l*DM, g_h2 + r*DM);
        __syncthreads();

        // ---- FFN1 -> g_f1 (ReLU) ----
        for (int i = t; i < M*FFH; i += NTH) {
            int m = i / FFH, n = i - m*FFH;
            const float* hp = g_h2 + m*DM;
            float acc = 0.f;
#pragma unroll 4
            for (int k = 0; k < DM; k++)
                acc = fmaf(hp[k], W1[(long long)k*FFH + n], acc);
            acc += P.b1[l*FFH + n];
            g_f1[i] = fmaxf(acc, 0.f);
        }
        __syncthreads();

        // ---- FFN2 -> g_r2 ----
        for (int i = t; i < M*DM; i += NTH) {
            int m = i / DM, n = i - m*DM;
            const float* fp = g_f1 + m*FFH;
            float acc = 0.f;
#pragma unroll 4
            for (int k = 0; k < FFH; k++)
                acc = fmaf(fp[k], W2[(long long)k*DM + n], acc);
            g_r2[i] = acc + P.b2[l*DM + n];
        }
        __syncthreads();

        // ---- LN2: g_h = LN(g_h2 + g_r2) ----
        for (int r = warp; r < M; r += 32)
            ln_row_warp(g_h2 + r*DM, g_r2 + r*DM,
                        P.ln2s + l*DM, P.ln2b + l*DM, g_h + r*DM);
        __syncthreads();
    }

    // ---- LM head + argmax over V, rows b*NC+NC-1 ----
    {
        const float* h0 = g_h + (0*NC + NC - 1)*DM;
        const float* h1 = g_h + (1*NC + NC - 1)*DM;
        const float* h2 = g_h + (2*NC + NC - 1)*DM;
        const float* h3 = g_h + (3*NC + NC - 1)*DM;
        unsigned long long b0 = 0ull, b1 = 0ull, b2 = 0ull, b3 = 0ull;
        for (int v = t; v < VSZ; v += NTH) {
            float a0 = 0.f, a1 = 0.f, a2 = 0.f, a3 = 0.f;
            const float* Wp = P.lmW + v;
#pragma unroll 4
            for (int k = 0; k < DM; k++) {
                float w = Wp[(long long)k*VSZ];
                a0 = fmaf(h0[k], w, a0);
                a1 = fmaf(h1[k], w, a1);
                a2 = fmaf(h2[k], w, a2);
                a3 = fmaf(h3[k], w, a3);
            }
            float lb = P.lmb[v];
            a0 += lb; a1 += lb; a2 += lb; a3 += lb;
            unsigned idx = 0xFFFFFFFFu - (unsigned)v;
            unsigned u0 = __float_as_uint(a0); u0 = (u0 & 0x80000000u) ? ~u0 : (u0 | 0x80000000u);
            unsigned u1 = __float_as_uint(a1); u1 = (u1 & 0x80000000u) ? ~u1 : (u1 | 0x80000000u);
            unsigned u2 = __float_as_uint(a2); u2 = (u2 & 0x80000000u) ? ~u2 : (u2 | 0x80000000u);
            unsigned u3 = __float_as_uint(a3); u3 = (u3 & 0x80000000u) ? ~u3 : (u3 | 0x80000000u);
            unsigned long long k0 = ((unsigned long long)u0 << 32) | idx;
            unsigned long long k1 = ((unsigned long long)u1 << 32) | idx;
            unsigned long long k2 = ((unsigned long long)u2 << 32) | idx;
            unsigned long long k3 = ((unsigned long long)u3 << 32) | idx;
            if (k0 > b0) b0 = k0;
            if (k1 > b1) b1 = k1;
            if (k2 > b2) b2 = k2;
            if (k3 > b3) b3 = k3;
        }
        for (int o = 16; o > 0; o >>= 1) {
            unsigned long long u;
            u = __shfl_xor_sync(0xffffffffu, b0, o); if (u > b0) b0 = u;
            u = __shfl_xor_sync(0xffffffffu, b1, o); if (u > b1) b1 = u;
            u = __shfl_xor_sync(0xffffffffu, b2, o); if (u > b2) b2 = u;
            u = __shfl_xor_sync(0xffffffffu, b3, o); if (u > b3) b3 = u;
        }
        if (lane == 0) {
            wbest[warp][0] = b0; wbest[warp][1] = b1;
            wbest[warp][2] = b2; wbest[warp][3] = b3;
        }
    }
    __syncthreads();
    if (warp == 0) {
        int newtok[4];
        for (int b = 0; b < 4; b++) {
            unsigned long long v = wbest[lane][b];
            for (int o = 16; o > 0; o >>= 1) {
                unsigned long long u = __shfl_xor_sync(0xffffffffu, v, o);
                if (u > v) v = u;
            }
            newtok[b] = (int)(0xFFFFFFFFu - (unsigned)(v & 0xFFFFFFFFu));
        }
        if (lane == 0) {
            bool alleos = true;
            for (int b = 0; b < 4; b++) {
                g_inp[b*SSQ + cl + 1] = newtok[b];
                P.out[b*32 + cl] = (float)newtok[b];    // float output
                if (newtok[b] != EOS_TOK) alleos = false;
            }
            if (alleos) g_stop = 1;
        }
    }
}

// ------------------------- host -------------------------
extern "C" void kernel_launch(void* const* d_in, const int* in_sizes, int n_in,
                              void* d_out, int out_size) {
    (void)in_sizes; (void)out_size;
    // insertion order: initial_words, [max_length], emb, Wq,bq,Wk,bk,Wv,bv,Wo,bo,
    //                  ln1s,ln1b,W1,b1,W2,b2,ln2s,ln2b,lmW,lmb
    int base = n_in - 19;
    const int* words = (const int*)d_in[0];
    Params P;
    P.emb  = (const float*)d_in[base + 0];
    P.Wq   = (const float*)d_in[base + 1];
    P.bq   = (const float*)d_in[base + 2];
    P.Wk   = (const float*)d_in[base + 3];
    P.bk   = (const float*)d_in[base + 4];
    P.Wv   = (const float*)d_in[base + 5];
    P.bv   = (const float*)d_in[base + 6];
    P.Wo   = (const float*)d_in[base + 7];
    P.bo   = (const float*)d_in[base + 8];
    P.ln1s = (const float*)d_in[base + 9];
    P.ln1b = (const float*)d_in[base + 10];
    P.W1   = (const float*)d_in[base + 11];
    P.b1   = (const float*)d_in[base + 12];
    P.W2   = (const float*)d_in[base + 13];
    P.b2   = (const float*)d_in[base + 14];
    P.ln2s = (const float*)d_in[base + 15];
    P.ln2b = (const float*)d_in[base + 16];
    P.lmW  = (const float*)d_in[base + 17];
    P.lmb  = (const float*)d_in[base + 18];
    P.out  = (float*)d_out;

    k_init<<<1, 256>>>(words, P.out);
    // prefill: positions 0..8, logits at cl=8 -> token for inp[9] (out col 8)
    step_one<9><<<1, NTH>>>(P, 0, 8);
    // decode: position p, logits at cl=p -> inp[p+1] (out col p)
    for (int p = 9; p <= 31; p++)
        step_one<1><<<1, NTH>>>(P, p, p);
}

// round 12
// speedup vs baseline: 35.7686x; 35.7686x over previous
#include <cuda_runtime.h>
#include <math.h>

#define VSZ 30000
#define DM  640
#define NL  6
#define NH  8
#define DHD 80
#define FFH 2560
#define BB  4
#define SSQ 33
#define EOS_TOK 2
#define NPART (VSZ/16)   // 1875
#define NBLK 148
#define NTHR 256

struct Params {
    const int* words;
    const float *emb,*Wq,*bq,*Wk,*bk,*Wv,*bv,*Wo,*bo;
    const float *ln1s,*ln1b,*W1,*b1,*W2,*b2,*ln2s,*ln2b,*lmW,*lmb;
    float* out;                       // __output__ dtype is float32 (proven R11)
};

// ------------------------- device state -------------------------
__device__ unsigned g_bar_count;
__device__ unsigned g_bar_gen;
__device__ int g_stop;
__device__ int g_inp[BB*SSQ];
__device__ unsigned long long g_best[BB];
__device__ float g_h [36*DM];
__device__ float g_q [36*DM];
__device__ float g_ao[36*DM];
__device__ float g_r1[36*DM];
__device__ float g_f1[36*FFH];
__device__ float g_r2[36*DM];
__device__ float g_kc[NL*BB*SSQ*DM];
__device__ float g_vc[NL*BB*SSQ*DM];

// ------------------------- grid barrier -------------------------
__device__ __forceinline__ void gsync(unsigned &gen) {
    __syncthreads();
    if (threadIdx.x == 0) {
        __threadfence();                       // release (gpu scope)
        unsigned arrived = atomicAdd(&g_bar_count, 1u);
        if (arrived == NBLK - 1u) {
            g_bar_count = 0u;
            __threadfence();
            atomicAdd(&g_bar_gen, 1u);
        } else {
            while (atomicAdd(&g_bar_gen, 0u) == gen) __nanosleep(64);
        }
        __threadfence();                       // acquire (L1D inval)
    }
    gen++;
    __syncthreads();
}

// ------------------------- generic small-M GEMM phase -------------------------
// A/out alias kernel-mutable globals: plain float* (no __ldg / no __restrict__).
// W/bias immutable weights: __ldg safe.
template<int M, int SLICES, bool RELU>
__device__ __forceinline__ void gemm_chunks(
    float* A, const float* __restrict__ W,
    const float* __restrict__ bias, float* out,
    int K, int N, float* s)
{
    constexpr int C = NTHR / SLICES;
    const int nch = N / C;
    const int t = threadIdx.x;
    const int c = t % C, ks = t / C;
    const int KL = K / SLICES;
    for (int ch = blockIdx.x; ch < nch; ch += NBLK) {
        int n = ch * C + c;
        float acc[M];
#pragma unroll
        for (int m = 0; m < M; m++) acc[m] = 0.f;
        const float* Wp = W + (long long)(ks*KL) * N + n;
        float* Ap = A + ks*KL;
#pragma unroll 8
        for (int kk = 0; kk < KL; kk++) {
            float w = __ldg(Wp); Wp += N;
#pragma unroll
            for (int m = 0; m < M; m++)
                acc[m] = fmaf(Ap[(long long)m*K + kk], w, acc[m]);
        }
        for (int m0 = 0; m0 < M; m0 += 8) {
            int mc = (M - m0 < 8) ? (M - m0) : 8;
            __syncthreads();
            for (int mi = 0; mi < mc; mi++) s[mi*NTHR + t] = acc[m0 + mi];
            __syncthreads();
            if (t < mc*C) {
                int mi = t / C, cc = t % C;
                float v = 0.f;
#pragma unroll
                for (int q = 0; q < SLICES; q++) v += s[mi*NTHR + q*C + cc];
                int nn = ch*C + cc;
                v += __ldg(bias + nn);
                if (RELU) v = fmaxf(v, 0.f);
                out[(m0 + mi)*N + nn] = v;
            }
        }
        __syncthreads();
    }
}

// ------------------------- fused QKV phase -------------------------
template<int NC>
__device__ __forceinline__ void qkv_phase(const Params& P, int l, int p0, float* s) {
    constexpr int M = 4*NC;
    const int t = threadIdx.x;
    const int c = t & 15, ks = t >> 4;
    const int KL = DM/16;     // 40
    for (int ch = blockIdx.x; ch < 120; ch += NBLK) {
        int sel = ch / 40, nb = ch % 40;
        const float* W    = (sel == 0) ? P.Wq : (sel == 1) ? P.Wk : P.Wv;
        const float* bias = (sel == 0) ? P.bq : (sel == 1) ? P.bk : P.bv;
        W    += (long long)l*DM*DM;
        bias += l*DM;
        int n = nb*16 + c;
        float acc[M];
#pragma unroll
        for (int m = 0; m < M; m++) acc[m] = 0.f;
        const float* Wp = W + (ks*KL)*DM + n;
        int kbase = ks*KL;
#pragma unroll 8
        for (int kk = 0; kk < KL; kk++) {
            float w = __ldg(Wp); Wp += DM;
#pragma unroll
            for (int m = 0; m < M; m++)
                acc[m] = fmaf(g_h[m*DM + kbase + kk], w, acc[m]);
        }
        for (int m0 = 0; m0 < M; m0 += 8) {
            int mc = (M - m0 < 8) ? (M - m0) : 8;
            __syncthreads();
            for (int mi = 0; mi < mc; mi++) s[mi*NTHR + t] = acc[m0 + mi];
            __syncthreads();
            if (t < mc*16) {
                int mi = t >> 4, cc = t & 15;
                float v = 0.f;
#pragma unroll
                for (int q = 0; q < 16; q++) v += s[mi*NTHR + q*16 + cc];
                int nn = nb*16 + cc;
                v += __ldg(bias + nn);
                int m = m0 + mi;
                int b = m / NC, j = m - b*NC;
                int p = p0 + j;
                if (sel == 0)      g_q[m*DM + nn] = v;
                else if (sel == 1) g_kc[((l*BB + b)*SSQ + p)*DM + nn] = v;
                else               g_vc[((l*BB + b)*SSQ + p)*DM + nn] = v;
            }
        }
        __syncthreads();
    }
}

// ------------------------- attention phase (one warp per (b,h,j)) -------------------------
template<int NC>
__device__ __forceinline__ void attn_phase(int l, int p0) {
    int warp = threadIdx.x >> 5, lane = threadIdx.x & 31;
    int total = BB*NH*NC;
    for (int tup = blockIdx.x*8 + warp; tup < total; tup += NBLK*8) {
        int b = tup / (NH*NC);
        int rem = tup - b*NH*NC;
        int h = rem / NC, j = rem - h*NC;
        int p = p0 + j, nk = p + 1;
        int r = b*NC + j;
        float* qp = g_q + r*DM + h*DHD;
        float sc = -1e30f;
        if (lane < nk) {
            float* kp = g_kc + ((l*BB + b)*SSQ + lane)*DM + h*DHD;
            float sv = 0.f;
#pragma unroll
            for (int d = 0; d < DHD; d++) sv = fmaf(qp[d], kp[d], sv);
            sc = sv / sqrtf((float)DHD);
        }
        float mx = sc;
        for (int o = 16; o > 0; o >>= 1) mx = fmaxf(mx, __shfl_xor_sync(0xffffffffu, mx, o));
        float e = (lane < nk) ? expf(sc - mx) : 0.f;
        float sum = e;
        for (int o = 16; o > 0; o >>= 1) sum += __shfl_xor_sync(0xffffffffu, sum, o);
        float o0 = 0.f, o1 = 0.f, o2 = 0.f;
        float* vb = g_vc + ((l*BB + b)*SSQ)*DM + h*DHD;
        for (int jk = 0; jk < nk; jk++) {
            float pj = __shfl_sync(0xffffffffu, e, jk) / sum;
            float* vp = vb + jk*DM;
            o0 = fmaf(pj, vp[lane],      o0);
            o1 = fmaf(pj, vp[lane + 32], o1);
            if (lane < 16) o2 = fmaf(pj, vp[lane + 64], o2);
        }
        float* ao = g_ao + r*DM + h*DHD;
        ao[lane] = o0; ao[lane + 32] = o1;
        if (lane < 16) ao[lane + 64] = o2;
    }
}

// ------------------------- LayerNorm phase: g_h = LN(g_h + res)*sc + bi -------------------------
template<int M>
__device__ __forceinline__ void ln_phase(float* res,
                                         const float* __restrict__ sc,
                                         const float* __restrict__ bi) {
    __shared__ float xs[DM];
    __shared__ float red[NTHR];
    __shared__ float mv[2];
    int t = threadIdx.x;
    for (int r = blockIdx.x; r < M; r += NBLK) {
        for (int d = t; d < DM; d += NTHR) xs[d] = g_h[r*DM + d] + res[r*DM + d];
        __syncthreads();
        float pp = 0.f;
        for (int d = t; d < DM; d += NTHR) pp += xs[d];
        red[t] = pp; __syncthreads();
        for (int st = 128; st > 0; st >>= 1) { if (t < st) red[t] += red[t + st]; __syncthreads(); }
        if (t == 0) mv[0] = red[0] / DM;
        __syncthreads();
        float mean = mv[0];
        pp = 0.f;
        for (int d = t; d < DM; d += NTHR) { float x = xs[d] - mean; pp += x*x; }
        red[t] = pp; __syncthreads();
        for (int st = 128; st > 0; st >>= 1) { if (t < st) red[t] += red[t + st]; __syncthreads(); }
        if (t == 0) mv[1] = red[0] / DM;
        __syncthreads();
        float dn = sqrtf(mv[1] + 1e-6f);
        for (int d = t; d < DM; d += NTHR)
            g_h[r*DM + d] = (xs[d] - mean) / dn * __ldg(sc + d) + __ldg(bi + d);
        __syncthreads();
    }
}

// ------------------------- LM head + argmax phase -------------------------
template<int NC>
__device__ __forceinline__ void lm_phase(const float* __restrict__ lmW,
                                         const float* __restrict__ lmb, float* s) {
    __shared__ unsigned long long sk[64];
    const int t = threadIdx.x;
    const int c = t & 15, ks = t >> 4;
    const int KL = DM/16;     // 40
    unsigned long long best = 0ull;
    for (int ch = blockIdx.x; ch < NPART; ch += NBLK) {
        float acc[4] = {0.f, 0.f, 0.f, 0.f};
        const float* Wp = lmW + (long long)(ks*KL) * VSZ + ch*16 + c;
        int kbase = ks*KL;
#pragma unroll 8
        for (int kk = 0; kk < KL; kk++) {
            float w = __ldg(Wp); Wp += VSZ;
#pragma unroll
            for (int b = 0; b < 4; b++)
                acc[b] = fmaf(g_h[(b*NC + NC - 1)*DM + kbase + kk], w, acc[b]);
        }
        __syncthreads();
        for (int b = 0; b < 4; b++) s[b*NTHR + t] = acc[b];
        __syncthreads();
        if (t < 64) {
            int b = t >> 4, cc = t & 15;
            float v = 0.f;
#pragma unroll
            for (int q = 0; q < 16; q++) v += s[b*NTHR + q*16 + cc];
            int n = ch*16 + cc;
            v += __ldg(lmb + n);
            unsigned u = __float_as_uint(v);
            u = (u & 0x80000000u) ? ~u : (u | 0x80000000u);
            unsigned long long key =
                ((unsigned long long)u << 32) | (unsigned)(0xFFFFFFFFu - (unsigned)n);
            if (key > best) best = key;
        }
    }
    __syncthreads();
    if (t < 64) sk[t] = best;
    __syncthreads();
    if (t < 4) {
        unsigned long long bb = sk[t*16];
        for (int i = 1; i < 16; i++) if (sk[t*16 + i] > bb) bb = sk[t*16 + i];
        if (bb) atomicMax(&g_best[t], bb);
    }
}

// ------------------------- one generation step -------------------------
template<int NC>
__device__ void do_step(int p0, int cl, const Params& P, unsigned &gen, float* s) {
    constexpr int M = 4*NC;
    // embed
    for (int r = blockIdx.x; r < M; r += NBLK) {
        int b = r / NC, j = r - b*NC;
        int tok = g_inp[b*SSQ + p0 + j];
        if (tok < 0 || tok >= VSZ) tok = 0;
        const float* e = P.emb + (long long)tok * DM;
        for (int d = threadIdx.x; d < DM; d += NTHR) g_h[r*DM + d] = __ldg(e + d);
    }
    gsync(gen);
    for (int l = 0; l < NL; l++) {
        qkv_phase<NC>(P, l, p0, s);                                          gsync(gen);
        attn_phase<NC>(l, p0);                                               gsync(gen);
        gemm_chunks<M,16,false>(g_ao, P.Wo + (long long)l*DM*DM,
                                P.bo + l*DM, g_r1, DM, DM, s);               gsync(gen);
        ln_phase<M>(g_r1, P.ln1s + l*DM, P.ln1b + l*DM);                     gsync(gen);
        gemm_chunks<M,16,true >(g_h, P.W1 + (long long)l*DM*FFH,
                                P.b1 + l*FFH, g_f1, DM, FFH, s);             gsync(gen);
        gemm_chunks<M,32,false>(g_f1, P.W2 + (long long)l*FFH*DM,
                                P.b2 + l*DM, g_r2, FFH, DM, s);              gsync(gen);
        ln_phase<M>(g_r2, P.ln2s + l*DM, P.ln2b + l*DM);                     gsync(gen);
    }
    lm_phase<NC>(P.lmW, P.lmb, s);                                           gsync(gen);
    if (blockIdx.x == 0 && threadIdx.x == 0) {
        bool alleos = true;
        for (int b = 0; b < BB; b++) {
            int tok = (int)(0xFFFFFFFFu - (unsigned)(g_best[b] & 0xFFFFFFFFu));
            g_inp[b*SSQ + cl + 1] = tok;
            if (tok != EOS_TOK) alleos = false;
            g_best[b] = 0ull;
        }
        if (alleos) g_stop = 1;
    }
    gsync(gen);
}

// ------------------------- the persistent mega-kernel -------------------------
__global__ __launch_bounds__(NTHR, 1)
void mega_kernel(Params P) {
    __shared__ float s[8*NTHR];
    __shared__ unsigned s_gen;
    if (threadIdx.x == 0) s_gen = atomicAdd(&g_bar_gen, 0u);
    __syncthreads();
    unsigned gen = s_gen;

    if (blockIdx.x == 0) {
        int t = threadIdx.x;
        if (t < BB*SSQ) g_inp[t] = 0;
        __syncthreads();
        if (t == 0) g_stop = 0;
        if (t < BB) { g_inp[t*SSQ] = 1; g_best[t] = 0ull; }
        if (t < 32) g_inp[(t >> 3)*SSQ + 1 + (t & 7)] = P.words[t];
    }
    gsync(gen);

    // prefill: positions 0..8, produces token for cl=8
    do_step<9>(0, 8, P, gen, s);
    // decode: cl = p, writes inp[p+1]
    for (int p = 9; p <= 31; p++) {
        if (*(volatile int*)&g_stop) break;   // uniform across blocks (post-barrier)
        do_step<1>(p, p, P, gen, s);
    }

    if (blockIdx.x == 0) {
        int t = threadIdx.x;
        if (t < BB*32) P.out[t] = (float)g_inp[(t >> 5)*SSQ + 1 + (t & 31)];
    }
}

// ------------------------- host -------------------------
extern "C" void kernel_launch(void* const* d_in, const int* in_sizes, int n_in,
                              void* d_out, int out_size) {
    (void)in_sizes; (void)out_size;
    // insertion order: initial_words, [max_length], emb, Wq,bq,Wk,bk,Wv,bv,Wo,bo,
    //                  ln1s,ln1b,W1,b1,W2,b2,ln2s,ln2b,lmW,lmb
    int base = n_in - 19;
    Params P;
    P.words = (const int*)d_in[0];
    P.emb  = (const float*)d_in[base + 0];
    P.Wq   = (const float*)d_in[base + 1];
    P.bq   = (const float*)d_in[base + 2];
    P.Wk   = (const float*)d_in[base + 3];
    P.bk   = (const float*)d_in[base + 4];
    P.Wv   = (const float*)d_in[base + 5];
    P.bv   = (const float*)d_in[base + 6];
    P.Wo   = (const float*)d_in[base + 7];
    P.bo   = (const float*)d_in[base + 8];
    P.ln1s = (const float*)d_in[base + 9];
    P.ln1b = (const float*)d_in[base + 10];
    P.W1   = (const float*)d_in[base + 11];
    P.b1   = (const float*)d_in[base + 12];
    P.W2   = (const float*)d_in[base + 13];
    P.b2   = (const float*)d_in[base + 14];
    P.ln2s = (const float*)d_in[base + 15];
    P.ln2b = (const float*)d_in[base + 16];
    P.lmW  = (const float*)d_in[base + 17];
    P.lmb  = (const float*)d_in[base + 18];
    P.out  = (float*)d_out;

    mega_kernel<<<NBLK, NTHR>>>(P);
}